// round 5
// baseline (speedup 1.0000x reference)
#include <cuda_runtime.h>
#include <cuda_fp16.h>

#define NN      131072
#define KK      27
#define C       32
#define CAP     96                 // bucket capacity (Poisson(27), P(overflow) ~ 2.5e-10)
#define BN_BLKS 1024
#define EPS_F   1e-5f
#define NPC     16                 // nodes per CTA in fused kernel
#define SSTR    868                // S stride per node in floats (864 + 4 pad: conflict-free)
#define FUSED_SMEM (NPC * SSTR * 4)   // 55552 B

// -------- device scratch --------
__device__ int    g_fill[NN];
__device__ __align__(16) int g_list[(size_t)NN * CAP];    // 50 MB inverse index (e = n*32+k)
__device__ __align__(8)  __half2 g_data16[NN * 16];       // 8 MB fp16 copy of data
__device__ __align__(8)  unsigned g_btf[27 * 4 * 4 * 32 * 2]; // 110 KB: W as tf32 B-frags
__device__ float  g_part[BN_BLKS * 64];
__device__ float  g_stats[64];

__device__ __forceinline__ unsigned f2tf32(float f) {
    unsigned r;
    asm("cvt.rna.tf32.f32 %0, %1;" : "=r"(r) : "f"(f));
    return r;
}

// -------- 1. init: zero fill, data->fp16, W->tf32 B-frags --------
// btf[((kb*4+s)*4+t)*32+l][r] = tf32( weight[kb][ s*8+(l&3)+r*4 ][ t*8+(l>>2) ] )
// (mma.m16n8k8 B layout: b0 row=lane&3, b1 row=(lane&3)+4, col=lane>>2)
__global__ void k_init(const float* __restrict__ data,
                       const float* __restrict__ weight) {
    int i = blockIdx.x * blockDim.x + threadIdx.x;       // < 524288
    if (i < NN) g_fill[i] = 0;
    // data -> fp16 (2 float4 per thread)
#pragma unroll
    for (int u = 0; u < 2; ++u) {
        int idx = i * 2 + u;                             // < 1048576 float4 units
        float4 v = reinterpret_cast<const float4*>(data)[idx];
        __half2 h0 = __floats2half2_rn(v.x, v.y);
        __half2 h1 = __floats2half2_rn(v.z, v.w);
        uint2 s;
        s.x = *reinterpret_cast<unsigned*>(&h0);
        s.y = *reinterpret_cast<unsigned*>(&h1);
        reinterpret_cast<uint2*>(g_data16)[idx] = s;
    }
    if (i < 27 * 1024) {
        int r = i & 1, l = (i >> 1) & 31, t = (i >> 6) & 3, s = (i >> 8) & 3, kb = i >> 10;
        int krow = s * 8 + (l & 3) + r * 4;              // inner-dim channel
        int ncol = t * 8 + (l >> 2);                     // output channel
        g_btf[i] = f2tf32(weight[(kb * 32 + krow) * 32 + ncol]);
    }
}

// -------- 2. build inverse index, bucketed by output node m --------
// stage neigh rows through smem for coalesced reads; store e = (n<<5)|k.
__global__ __launch_bounds__(256) void k_fill(const int* __restrict__ neigh) {
    __shared__ int sn[256 * KK];
    int base = blockIdx.x * 256;
    for (int i = threadIdx.x; i < 256 * KK; i += 256)
        sn[i] = neigh[(size_t)base * KK + i];
    __syncthreads();
    int n = base + threadIdx.x;
#pragma unroll
    for (int j = 0; j < KK; ++j) {
        int m   = sn[threadIdx.x * KK + j];
        int pos = atomicAdd(&g_fill[m], 1);
        if (pos < CAP) g_list[(size_t)m * CAP + pos] = (n << 5) | j;
    }
}

// -------- 3. fused gather + tf32 GEMM --------
// warp = output node: phase A sums data16 rows into S[node][k][ch] (fp32 smem);
// phase B: out[16x32] = S[16x864] @ Wcat[864x32] via mma.m16n8k8.tf32,
// 16 warps over 27 k-blocks, deterministic staged reduction (S reused).
__global__ __launch_bounds__(512) void k_fused(float* __restrict__ out) {
    extern __shared__ float S[];
    const int tid = threadIdx.x, lane = tid & 31, w = tid >> 5;   // w = local node / warp
    const int node_g = blockIdx.x * NPC + w;

    // ---- phase A ----
    float* Sn = S + w * SSTR;
    for (int j = lane; j < 864; j += 32) Sn[j] = 0.f;

    int cnt = g_fill[node_g];
    if (cnt > CAP) cnt = CAP;
    const int* lst = g_list + (size_t)node_g * CAP;
    const int hsel = lane & 1;            // low/high half of the half2
    const int c2   = lane >> 1;           // half2 index (2 lanes share, broadcast)

    int e_next = (cnt > 0) ? lst[0] : 0;
    for (int j = 0; j < cnt; ++j) {
        int e = e_next;
        if (j + 1 < cnt) e_next = lst[j + 1];
        int n = e >> 5, k = e & 31;
        __half2 h = g_data16[n * 16 + c2];
        float v = hsel ? __high2float(h) : __low2float(h);
        Sn[k * 32 + lane] += v;
    }
    __syncthreads();

    // ---- phase B ----
    float d[4][4];
#pragma unroll
    for (int t = 0; t < 4; ++t)
#pragma unroll
        for (int q = 0; q < 4; ++q) d[t][q] = 0.f;

    const int r0 = lane >> 2, cA = lane & 3;
    for (int pass = 0; pass < 2; ++pass) {
        int kb = w + pass * 16;
        if (kb >= KK) break;
#pragma unroll
        for (int s = 0; s < 4; ++s) {
            const float* Ab = S + kb * 32 + s * 8 + cA;
            unsigned a0 = f2tf32(Ab[(r0    ) * SSTR    ]);
            unsigned a1 = f2tf32(Ab[(r0 + 8) * SSTR    ]);
            unsigned a2 = f2tf32(Ab[(r0    ) * SSTR + 4]);
            unsigned a3 = f2tf32(Ab[(r0 + 8) * SSTR + 4]);
            const uint2* bp = reinterpret_cast<const uint2*>(g_btf) +
                              ((kb * 4 + s) * 4) * 32 + lane;
#pragma unroll
            for (int t = 0; t < 4; ++t) {
                uint2 b = bp[t * 32];
                asm volatile(
                    "mma.sync.aligned.m16n8k8.row.col.f32.tf32.tf32.f32 "
                    "{%0,%1,%2,%3}, {%4,%5,%6,%7}, {%8,%9}, {%0,%1,%2,%3};"
                    : "+f"(d[t][0]), "+f"(d[t][1]), "+f"(d[t][2]), "+f"(d[t][3])
                    : "r"(a0), "r"(a1), "r"(a2), "r"(a3), "r"(b.x), "r"(b.y));
            }
        }
    }
    __syncthreads();                      // all S reads done; reuse S for partials

    // stage per-warp partials: P[w][16][32]
    float* P = S + w * 512;
#pragma unroll
    for (int t = 0; t < 4; ++t) {
        *reinterpret_cast<float2*>(&P[(r0    ) * 32 + t * 8 + cA * 2]) =
            make_float2(d[t][0], d[t][1]);
        *reinterpret_cast<float2*>(&P[(r0 + 8) * 32 + t * 8 + cA * 2]) =
            make_float2(d[t][2], d[t][3]);
    }
    __syncthreads();

    // deterministic reduction over 16 warps; coalesced write
    float acc = 0.f;
#pragma unroll
    for (int ww = 0; ww < 16; ++ww) acc += S[ww * 512 + tid];
    out[(size_t)blockIdx.x * 512 + tid] = acc;
}

// -------- 4. BN stats, stage 1 --------
__global__ __launch_bounds__(256) void k_bnpart(const float* __restrict__ out) {
    __shared__ float ss[8][32], sq[8][32];
    int ch = threadIdx.x & 31, w = threadIdx.x >> 5;
    int r0 = blockIdx.x * (NN / BN_BLKS);
    float s = 0.f, q = 0.f;
    for (int r = r0 + w; r < r0 + (NN / BN_BLKS); r += 8) {
        float v = out[(size_t)r * C + ch];
        s += v;
        q += v * v;
    }
    ss[w][ch] = s;
    sq[w][ch] = q;
    __syncthreads();
    if (w == 0) {
        float S = 0.f, Q = 0.f;
#pragma unroll
        for (int t = 0; t < 8; ++t) { S += ss[t][ch]; Q += sq[t][ch]; }
        g_part[blockIdx.x * 64 + ch]      = S;
        g_part[blockIdx.x * 64 + 32 + ch] = Q;
    }
}

// -------- 5. BN stats, stage 2 --------
__global__ __launch_bounds__(256) void k_bnfinal(const float* __restrict__ gamma,
                                                 const float* __restrict__ beta) {
    __shared__ float ss[8][32], sq[8][32];
    int ch = threadIdx.x & 31, w = threadIdx.x >> 5;
    float S = 0.f, Q = 0.f;
    for (int b = w; b < BN_BLKS; b += 8) {
        S += g_part[b * 64 + ch];
        Q += g_part[b * 64 + 32 + ch];
    }
    ss[w][ch] = S;
    sq[w][ch] = Q;
    __syncthreads();
    if (w == 0) {
        float St = 0.f, Qt = 0.f;
#pragma unroll
        for (int t = 0; t < 8; ++t) { St += ss[t][ch]; Qt += sq[t][ch]; }
        float mean  = St * (1.0f / NN);
        float var   = Qt * (1.0f / NN) - mean * mean;
        float rstd  = rsqrtf(var + EPS_F);
        float scale = gamma[ch] * rstd;
        g_stats[ch]      = scale;
        g_stats[32 + ch] = beta[ch] - mean * scale;
    }
}

// -------- 6. apply BN + ReLU --------
__global__ __launch_bounds__(256) void k_apply(float* __restrict__ out) {
    int i = blockIdx.x * blockDim.x + threadIdx.x;
    if (i >= NN * C) return;
    int   ch = i & 31;
    float y  = fmaf(out[i], g_stats[ch], g_stats[32 + ch]);
    out[i] = fmaxf(y, 0.f);
}

extern "C" void kernel_launch(void* const* d_in, const int* in_sizes, int n_in,
                              void* d_out, int out_size) {
    const float* data   = (const float*)d_in[0];
    const float* weight = (const float*)d_in[1];
    const float* gamma  = (const float*)d_in[2];
    const float* beta   = (const float*)d_in[3];
    const int*   neigh  = (const int*)d_in[4];
    float*       out    = (float*)d_out;

    cudaFuncSetAttribute(k_fused, cudaFuncAttributeMaxDynamicSharedMemorySize,
                         FUSED_SMEM);

    k_init<<<2048, 256>>>(data, weight);
    k_fill<<<NN / 256, 256>>>(neigh);
    k_fused<<<NN / NPC, 512, FUSED_SMEM>>>(out);
    k_bnpart<<<BN_BLKS, 256>>>(out);
    k_bnfinal<<<1, 256>>>(gamma, beta);
    k_apply<<<(NN * C + 255) / 256, 256>>>(out);
}